// round 6
// baseline (speedup 1.0000x reference)
#include <cuda_runtime.h>
#include <math.h>

// Problem constants (fixed shapes for this problem)
#define NN 50000
#define EE 800000

// -------- device scratch (allocation-free: __device__ globals) --------
__device__ float g_dis[NN];
__device__ int   g_cnt[NN];
__device__ int   g_ptr[NN + 1];
__device__ int   g_wp[NN];
__device__ int   g_csr[EE];
__device__ float g_M2[128 * 512];
__device__ float g_M[128 * 16];
__device__ float g_Wcat[128 * 32];
__device__ float g_xw[(size_t)NN * 32];
__device__ float g_h0[(size_t)NN * 16];
__device__ float g_bufR[(size_t)NN * 256];   // raw GEMM output (pre-aggregation)
__device__ float g_bufF[(size_t)NN * 256];   // aggregated + elu features
__device__ float g_sa[(size_t)NN * 16];
__device__ float g_da[(size_t)NN * 16];

// -------- helpers --------
__device__ __forceinline__ float eluf(float v)  { return v > 0.f ? v : expm1f(v); }
__device__ __forceinline__ float lrelu(float v) { return v > 0.f ? v : 0.2f * v; }

__device__ __forceinline__ unsigned long long dup2(float x) {
    unsigned long long r;
    asm("mov.b64 %0, {%1, %1};" : "=l"(r) : "f"(x));
    return r;
}
__device__ __forceinline__ void fma2(unsigned long long& d, unsigned long long a, unsigned long long b) {
    asm("fma.rn.f32x2 %0, %1, %2, %0;" : "+l"(d) : "l"(a), "l"(b));
}
__device__ __forceinline__ void unpack2(unsigned long long v, float& lo, float& hi) {
    asm("mov.b64 {%0, %1}, %2;" : "=f"(lo), "=f"(hi) : "l"(v));
}

// -------- CSR build --------
__global__ void k_zero(int n) {
    int i = blockIdx.x * blockDim.x + threadIdx.x;
    if (i < n) g_cnt[i] = 0;
}

__global__ void k_count(const int* __restrict__ ei, int E) {
    int e = blockIdx.x * blockDim.x + threadIdx.x;
    if (e < E) atomicAdd(&g_cnt[ei[E + e]], 1);
}

// single-block exclusive scan of g_cnt -> g_ptr, g_wp; also dis = rsqrt(indeg+1)
__global__ void k_scan(int n) {
    __shared__ int wsum[32];
    __shared__ int s_carry;
    int tid = threadIdx.x, lane = tid & 31, wid = tid >> 5;
    if (tid == 0) s_carry = 0;
    __syncthreads();
    for (int base = 0; base < n; base += 1024) {
        int i = base + tid;
        int v = (i < n) ? g_cnt[i] : 0;
        int incl = v;
        #pragma unroll
        for (int off = 1; off < 32; off <<= 1) {
            int y = __shfl_up_sync(0xffffffffu, incl, off);
            if (lane >= off) incl += y;
        }
        if (lane == 31) wsum[wid] = incl;
        __syncthreads();
        if (wid == 0) {
            int s = wsum[lane];
            #pragma unroll
            for (int off = 1; off < 32; off <<= 1) {
                int y = __shfl_up_sync(0xffffffffu, s, off);
                if (lane >= off) s += y;
            }
            wsum[lane] = s;
        }
        __syncthreads();
        int ex = s_carry + (wid ? wsum[wid - 1] : 0) + incl - v;
        if (i < n) {
            g_ptr[i] = ex;
            g_wp[i]  = ex;
            g_dis[i] = rsqrtf((float)v + 1.0f);  // +1 for self loop
        }
        int tot = wsum[31];
        __syncthreads();
        if (tid == 0) s_carry += tot;
        __syncthreads();
    }
    if (tid == 0) g_ptr[n] = s_carry;
}

__global__ void k_scatter(const int* __restrict__ ei, int E) {
    int e = blockIdx.x * blockDim.x + threadIdx.x;
    if (e < E) {
        int s = ei[e], d = ei[E + e];
        int p = atomicAdd(&g_wp[d], 1);
        g_csr[p] = s;
    }
}

// -------- small GEMMs for dual-conv weight collapse --------
// stage 0: g_M2[128,512] = Wd[128,512] @ Hd[512,512]
// stage 1: g_M [128,16]  = g_M2 @ Wr[512,16]
__global__ void k_dualgemm(const float* __restrict__ Aext, const float* __restrict__ Bext,
                           int M, int N, int K, int stage) {
    __shared__ float As[16][16];
    __shared__ float Bs[16][17];
    const float* A = stage ? (const float*)g_M2 : Aext;
    const float* B = Bext;
    float* C = stage ? g_M : g_M2;
    int tx = threadIdx.x, ty = threadIdx.y;
    int row = blockIdx.y * 16 + ty, col = blockIdx.x * 16 + tx;
    float acc = 0.f;
    for (int k0 = 0; k0 < K; k0 += 16) {
        As[ty][tx] = (row < M) ? A[(size_t)row * K + k0 + tx] : 0.f;
        Bs[ty][tx] = (col < N) ? B[(size_t)(k0 + ty) * N + col] : 0.f;
        __syncthreads();
        #pragma unroll
        for (int k = 0; k < 16; k++) acc += As[ty][k] * Bs[k][tx];
        __syncthreads();
    }
    if (row < M && col < N) C[(size_t)row * N + col] = acc;
}

__global__ void k_concat(const float* __restrict__ Wgcn) {
    int i = blockIdx.x * blockDim.x + threadIdx.x;
    if (i < 128 * 32) {
        int r = i >> 5, c = i & 31;
        g_Wcat[i] = (c < 16) ? Wgcn[r * 16 + c] : g_M[r * 16 + (c - 16)];
    }
}

// -------- XW: g_xw[N,32] = x[N,128] @ Wcat[128,32] (cols 0..15 GCN, 16..31 dual) --------
__global__ void __launch_bounds__(256) k_xw(const float* __restrict__ x, int n) {
    __shared__ __align__(16) float ws[128][32];
    __shared__ __align__(16) float xs[32][128];
    int tid = threadIdx.x;
    #pragma unroll
    for (int i = 0; i < 16; i++) { int f = tid + 256 * i; ws[f >> 5][f & 31] = g_Wcat[f]; }
    int r0 = blockIdx.x * 32;
    #pragma unroll
    for (int i = 0; i < 4; i++) {
        int idx = tid + 256 * i;
        int row = idx >> 5, c4 = idx & 31;
        float4 v = make_float4(0.f, 0.f, 0.f, 0.f);
        if (r0 + row < n) v = *(const float4*)&x[(size_t)(r0 + row) * 128 + c4 * 4];
        *(float4*)&xs[row][c4 * 4] = v;
    }
    __syncthreads();
    int c = tid & 31, rg = tid >> 5;
    float acc[4] = {0.f, 0.f, 0.f, 0.f};
    for (int k = 0; k < 128; k++) {
        float wv = ws[k][c];
        acc[0] += xs[rg][k] * wv;
        acc[1] += xs[rg + 8][k] * wv;
        acc[2] += xs[rg + 16][k] * wv;
        acc[3] += xs[rg + 24][k] * wv;
    }
    #pragma unroll
    for (int i = 0; i < 4; i++) {
        int row = r0 + rg + 8 * i;
        if (row < n) g_xw[(size_t)row * 32 + c] = acc[i];
    }
}

// -------- GCN aggregation + dual + bias + elu -> g_h0[N,16] --------
__global__ void k_gcn(const float* __restrict__ bgcn, int n) {
    int w = (blockIdx.x * blockDim.x + threadIdx.x) >> 5;
    if (w >= n) return;
    int lane = threadIdx.x & 31;
    int d = lane & 15;
    int beg = g_ptr[w], end = g_ptr[w + 1];
    float acc = 0.f;
    for (int e = beg + (lane >> 4); e < end; e += 2) {
        int s = g_csr[e];
        acc += g_dis[s] * g_xw[(size_t)s * 32 + d];
    }
    acc += __shfl_xor_sync(0xffffffffu, acc, 16);
    float dd = g_dis[w];
    acc *= dd;
    acc += dd * dd * g_xw[(size_t)w * 32 + d];          // self loop
    float v = acc + bgcn[d] + g_xw[(size_t)w * 32 + 16 + d];  // + dual conv
    v = eluf(v);
    if (lane < 16) g_h0[(size_t)w * 16 + d] = v;
}

// -------- GAT GEMM (f32x2 FFMA2): raw = in @ W; fused sa/da epilogue --------
// in = (K==16) ? g_h0 : g_bufF ; raw -> g_bufR ; sa/da -> g_sa/g_da
__global__ void __launch_bounds__(256) k_gatgemm(int K,
        const float* __restrict__ W,
        const float* __restrict__ asrc, const float* __restrict__ adst, int n) {
    __shared__ __align__(16) float hsT[16][68];
    __shared__ __align__(16) float Ws[16][256];
    __shared__ float s_as[256], s_ad[256];
    const float* __restrict__ in = (K == 16) ? (const float*)g_h0 : (const float*)g_bufF;
    float* __restrict__ raw = g_bufR;

    int tid = threadIdx.x;
    int tx = tid & 31, ty = tid >> 5;
    int r0 = blockIdx.x * 64;
    s_as[tid] = asrc[tid];
    s_ad[tid] = adst[tid];

    unsigned long long acc[8][4];
    #pragma unroll
    for (int i = 0; i < 8; i++)
        #pragma unroll
        for (int j = 0; j < 4; j++) acc[i][j] = 0ull;

    for (int k0 = 0; k0 < K; k0 += 16) {
        __syncthreads();
        {   // load input tile transposed -> hsT[k][row]
            int row = tid >> 2, kk = (tid & 3) * 4;
            float4 v = make_float4(0.f, 0.f, 0.f, 0.f);
            if (r0 + row < n) v = *(const float4*)&in[(size_t)(r0 + row) * K + k0 + kk];
            hsT[kk + 0][row] = v.x; hsT[kk + 1][row] = v.y;
            hsT[kk + 2][row] = v.z; hsT[kk + 3][row] = v.w;
        }
        #pragma unroll
        for (int i = 0; i < 4; i++) {   // load W tile [16,256]
            int f = tid + 256 * i;
            int kk = f >> 6, c4 = (f & 63) * 4;
            *(float4*)&Ws[kk][c4] = *(const float4*)&W[(size_t)(k0 + kk) * 256 + c4];
        }
        __syncthreads();
        #pragma unroll
        for (int k = 0; k < 16; k++) {
            float4 ha = *(const float4*)&hsT[k][ty * 8];
            float4 hb = *(const float4*)&hsT[k][ty * 8 + 4];
            const unsigned long long* wp = (const unsigned long long*)&Ws[k][tx * 8];
            unsigned long long wv0 = wp[0], wv1 = wp[1], wv2 = wp[2], wv3 = wp[3];
            unsigned long long hd[8];
            hd[0] = dup2(ha.x); hd[1] = dup2(ha.y); hd[2] = dup2(ha.z); hd[3] = dup2(ha.w);
            hd[4] = dup2(hb.x); hd[5] = dup2(hb.y); hd[6] = dup2(hb.z); hd[7] = dup2(hb.w);
            #pragma unroll
            for (int i = 0; i < 8; i++) {
                fma2(acc[i][0], hd[i], wv0);
                fma2(acc[i][1], hd[i], wv1);
                fma2(acc[i][2], hd[i], wv2);
                fma2(acc[i][3], hd[i], wv3);
            }
        }
    }

    // epilogue: store raw; compute sa/da (head = tx>>1; pair (tx, tx^1) covers a head)
    int head = tx >> 1;
    int chbase = (tx & 1) * 8;
    #pragma unroll
    for (int i = 0; i < 8; i++) {
        int row = r0 + ty * 8 + i;
        float c[8];
        #pragma unroll
        for (int j = 0; j < 4; j++) unpack2(acc[i][j], c[2 * j], c[2 * j + 1]);
        if (row < n) {
            float4 A = make_float4(c[0], c[1], c[2], c[3]);
            float4 B = make_float4(c[4], c[5], c[6], c[7]);
            *(float4*)&raw[(size_t)row * 256 + tx * 8]     = A;
            *(float4*)&raw[(size_t)row * 256 + tx * 8 + 4] = B;
        }
        float psa = 0.f, pda = 0.f;
        #pragma unroll
        for (int j = 0; j < 8; j++) {
            psa += c[j] * s_as[head * 16 + chbase + j];
            pda += c[j] * s_ad[head * 16 + chbase + j];
        }
        psa += __shfl_xor_sync(0xffffffffu, psa, 1);
        pda += __shfl_xor_sync(0xffffffffu, pda, 1);
        if (row < n) {
            if ((tx & 1) == 0) g_sa[(size_t)row * 16 + head] = psa;
            else               g_da[(size_t)row * 16 + head] = pda;
        }
    }
}

// -------- GAT aggregation: per-dst softmax attention; out = elu(agg + b) -> g_bufF --------
__global__ void k_gatagg(const float* __restrict__ bias, int n) {
    const float* __restrict__ raw = g_bufR;
    float* __restrict__ outF = g_bufF;
    int w = (blockIdx.x * blockDim.x + threadIdx.x) >> 5;
    if (w >= n) return;
    int lane = threadIdx.x & 31;
    int h16 = lane & 15;
    int beg = g_ptr[w], end = g_ptr[w + 1];
    float dval = g_da[(size_t)w * 16 + h16];
    float sa_self = g_sa[(size_t)w * 16 + h16];

    // pass 1: per-head max (two half-warps process alternating edges)
    float mx = lrelu(sa_self + dval);   // self loop
    for (int e = beg + (lane >> 4); e < end; e += 2) {
        int s = g_csr[e];
        mx = fmaxf(mx, lrelu(g_sa[(size_t)s * 16 + h16] + dval));
    }
    mx = fmaxf(mx, __shfl_xor_sync(0xffffffffu, mx, 16));

    // pass 2: weighted accumulation, lane covers channels [lane*8, lane*8+8), head = lane>>1
    float z = 0.f;
    float acc[8] = {0.f,0.f,0.f,0.f,0.f,0.f,0.f,0.f};
    {   // self loop
        float eh = __expf(lrelu(sa_self + dval) - mx);
        if (lane < 16) z += eh;
        float ew = __shfl_sync(0xffffffffu, eh, lane >> 1);
        const float4* hp = (const float4*)&raw[(size_t)w * 256 + lane * 8];
        float4 v0 = hp[0], v1 = hp[1];
        acc[0] += ew * v0.x; acc[1] += ew * v0.y; acc[2] += ew * v0.z; acc[3] += ew * v0.w;
        acc[4] += ew * v1.x; acc[5] += ew * v1.y; acc[6] += ew * v1.z; acc[7] += ew * v1.w;
    }
    for (int e = beg; e < end; e++) {
        int s = g_csr[e];
        float eh = __expf(lrelu(g_sa[(size_t)s * 16 + h16] + dval) - mx);
        if (lane < 16) z += eh;
        float ew = __shfl_sync(0xffffffffu, eh, lane >> 1);
        const float4* hp = (const float4*)&raw[(size_t)s * 256 + lane * 8];
        float4 v0 = hp[0], v1 = hp[1];
        acc[0] += ew * v0.x; acc[1] += ew * v0.y; acc[2] += ew * v0.z; acc[3] += ew * v0.w;
        acc[4] += ew * v1.x; acc[5] += ew * v1.y; acc[6] += ew * v1.z; acc[7] += ew * v1.w;
    }
    float zh = __shfl_sync(0xffffffffu, z, lane >> 1) + 1e-16f;
    float inv = 1.0f / zh;
    const float* bp = &bias[lane * 8];
    float4 o0, o1;
    o0.x = eluf(acc[0] * inv + bp[0]); o0.y = eluf(acc[1] * inv + bp[1]);
    o0.z = eluf(acc[2] * inv + bp[2]); o0.w = eluf(acc[3] * inv + bp[3]);
    o1.x = eluf(acc[4] * inv + bp[4]); o1.y = eluf(acc[5] * inv + bp[5]);
    o1.z = eluf(acc[6] * inv + bp[6]); o1.w = eluf(acc[7] * inv + bp[7]);
    *(float4*)&outF[(size_t)w * 256 + lane * 8]     = o0;
    *(float4*)&outF[(size_t)w * 256 + lane * 8 + 4] = o1;
}

// -------- final: concat(h[user], h[item]) @ Wdnn[512,2] -> log_softmax --------
__global__ void k_final(const float* __restrict__ Wdnn, const int* __restrict__ ui,
                        const int* __restrict__ ii, float* __restrict__ out, int Pn) {
    int p = (blockIdx.x * blockDim.x + threadIdx.x) >> 5;
    if (p >= Pn) return;
    int lane = threadIdx.x & 31;
    int u = ui[p], it = ii[p];
    float a0 = 0.f, a1 = 0.f;
    for (int i = lane; i < 512; i += 32) {
        float f = (i < 256) ? g_bufF[(size_t)u * 256 + i] : g_bufF[(size_t)it * 256 + (i - 256)];
        a0 += f * Wdnn[2 * i];
        a1 += f * Wdnn[2 * i + 1];
    }
    #pragma unroll
    for (int o = 16; o; o >>= 1) {
        a0 += __shfl_xor_sync(0xffffffffu, a0, o);
        a1 += __shfl_xor_sync(0xffffffffu, a1, o);
    }
    if (lane == 0) {
        float m = fmaxf(a0, a1);
        float l = logf(expf(a0 - m) + expf(a1 - m));
        out[2 * p]     = a0 - m - l;
        out[2 * p + 1] = a1 - m - l;
    }
}

extern "C" void kernel_launch(void* const* d_in, const int* in_sizes, int n_in,
                              void* d_out, int out_size) {
    const float* x    = (const float*)d_in[0];
    const int*   ei   = (const int*)d_in[1];
    const float* Hd   = (const float*)d_in[2];
    const int*   ui   = (const int*)d_in[3];
    const int*   ii   = (const int*)d_in[4];
    const float* Wgcn = (const float*)d_in[5];
    const float* bgcn = (const float*)d_in[6];
    const float* W1   = (const float*)d_in[7];
    const float* a1s  = (const float*)d_in[8];
    const float* a1d  = (const float*)d_in[9];
    const float* b1   = (const float*)d_in[10];
    const float* W2   = (const float*)d_in[11];
    const float* a2s  = (const float*)d_in[12];
    const float* a2d  = (const float*)d_in[13];
    const float* b2   = (const float*)d_in[14];
    const float* W3   = (const float*)d_in[15];
    const float* a3s  = (const float*)d_in[16];
    const float* a3d  = (const float*)d_in[17];
    const float* b3   = (const float*)d_in[18];
    const float* Wd   = (const float*)d_in[19];
    const float* Wr   = (const float*)d_in[20];
    const float* Wdnn = (const float*)d_in[21];
    float* out = (float*)d_out;

    int N = in_sizes[0] / 128;
    int E = in_sizes[1] / 2;
    int P = in_sizes[3];

    // CSR build + degrees
    k_zero<<<(N + 255) / 256, 256>>>(N);
    k_count<<<(E + 255) / 256, 256>>>(ei, E);
    k_scan<<<1, 1024>>>(N);
    k_scatter<<<(E + 255) / 256, 256>>>(ei, E);

    // dual conv weight collapse: M = Wd @ Hd @ Wr  (128x16)
    k_dualgemm<<<dim3(32, 8), dim3(16, 16)>>>(Wd, Hd, 128, 512, 512, 0);
    k_dualgemm<<<dim3(1, 8),  dim3(16, 16)>>>(Wd, Wr, 128, 16, 512, 1);
    k_concat<<<16, 256>>>(Wgcn);

    // xw = x @ [W_gcn | M]  (N x 32)
    k_xw<<<(N + 31) / 32, 256>>>(x, N);

    // GCN stage -> h0 [N,16]
    k_gcn<<<(N + 7) / 8, 256>>>(bgcn, N);

    int gB = (N + 63) / 64;
    int gA = (N + 7) / 8;

    // GAT layer 1
    k_gatgemm<<<gB, 256>>>(16, W1, a1s, a1d, N);
    k_gatagg<<<gA, 256>>>(b1, N);
    // GAT layer 2
    k_gatgemm<<<gB, 256>>>(256, W2, a2s, a2d, N);
    k_gatagg<<<gA, 256>>>(b2, N);
    // GAT layer 3
    k_gatgemm<<<gB, 256>>>(256, W3, a3s, a3d, N);
    k_gatagg<<<gA, 256>>>(b3, N);

    // final DNN + log_softmax
    k_final<<<(P + 7) / 8, 256>>>(Wdnn, ui, ii, out, P);
}